// round 1
// baseline (speedup 1.0000x reference)
#include <cuda_runtime.h>
#include <math.h>

#define EPSF 1e-8f
#define BB 64
#define NN 1024
#define WW 128

__device__ __forceinline__ float warp_sum(float v) {
#pragma unroll
    for (int o = 16; o; o >>= 1) v += __shfl_xor_sync(0xffffffffu, v, o);
    return v;
}
__device__ __forceinline__ float warp_max(float v) {
#pragma unroll
    for (int o = 16; o; o >>= 1) v = fmaxf(v, __shfl_xor_sync(0xffffffffu, v, o));
    return v;
}

// One block per batch b. 256 threads = 8 warps.
// Computes c_weights (cosine-sim softmax), w_weights, precedence_new.
__global__ __launch_bounds__(256) void wh_weights_kernel(
    const float* __restrict__ w_key, const float* __restrict__ w_beta,
    const float* __restrict__ a_gate, const float* __restrict__ w_gate,
    const float* __restrict__ alloc, const float* __restrict__ memory,
    const float* __restrict__ prec,
    float* __restrict__ out_w, float* __restrict__ out_prec)
{
    const int b = blockIdx.x;
    const int t = threadIdx.x;
    const int lane = t & 31;
    const int warp = t >> 5;

    __shared__ float s_key[WW];
    __shared__ float s_sim[NN];
    __shared__ float s_red[8];

    if (t < WW) s_key[t] = w_key[b * WW + t];
    __syncthreads();

    // per-warp key norm (computed redundantly by each warp; trivial cost)
    float ks = 0.f;
#pragma unroll
    for (int i = lane; i < WW; i += 32) { float v = s_key[i]; ks += v * v; }
    ks = warp_sum(ks);
    const float knorm = sqrtf(ks) + EPSF;

    // beta = 1 + softplus(w_beta)  (stable)
    const float bx = w_beta[b];
    const float beta = 1.f + (bx > 20.f ? bx : log1pf(expf(bx)));

    const float4 k4 = reinterpret_cast<const float4*>(s_key)[lane];

    // warp-per-row cosine similarity over memory[b, n, :]
    for (int n = warp; n < NN; n += 8) {
        const float4 m = reinterpret_cast<const float4*>(
            memory + ((size_t)b * NN + n) * WW)[lane];
        float dot = m.x * k4.x + m.y * k4.y + m.z * k4.z + m.w * k4.w;
        float sq  = m.x * m.x + m.y * m.y + m.z * m.z + m.w * m.w;
        dot = warp_sum(dot);
        sq  = warp_sum(sq);
        if (lane == 0)
            s_sim[n] = beta * dot / ((sqrtf(sq) + EPSF) * knorm);
    }
    __syncthreads();

    // ---- softmax over s_sim[0..N) ----
    float mx = -INFINITY;
#pragma unroll
    for (int r = 0; r < 4; r++) mx = fmaxf(mx, s_sim[t + r * 256]);
    mx = warp_max(mx);
    if (lane == 0) s_red[warp] = mx;
    __syncthreads();
    mx = s_red[0];
#pragma unroll
    for (int i = 1; i < 8; i++) mx = fmaxf(mx, s_red[i]);

    float ev[4];
    float esum = 0.f;
#pragma unroll
    for (int r = 0; r < 4; r++) {
        float e = expf(s_sim[t + r * 256] - mx);
        ev[r] = e;
        esum += e;
    }
    __syncthreads();                    // done reading s_red (max stage)
    esum = warp_sum(esum);
    if (lane == 0) s_red[warp] = esum;
    __syncthreads();
    float ssum = s_red[0];
#pragma unroll
    for (int i = 1; i < 8; i++) ssum += s_red[i];
    const float inv = 1.f / ssum;

    // ---- gated write weights + precedence ----
    const float wg = 1.f / (1.f + expf(-w_gate[b]));
    const float ag = 1.f / (1.f + expf(-a_gate[b]));

    float wv[4];
    float wsum = 0.f;
#pragma unroll
    for (int r = 0; r < 4; r++) {
        const int n = t + r * 256;
        const float c = ev[r] * inv;
        const float w = wg * (ag * alloc[(size_t)b * NN + n] + (1.f - ag) * c);
        wv[r] = w;
        wsum += w;
        out_w[(size_t)b * NN + n] = w;
    }
    __syncthreads();                    // done reading s_red (sum stage)
    wsum = warp_sum(wsum);
    if (lane == 0) s_red[warp] = wsum;
    __syncthreads();
    float tot = s_red[0];
#pragma unroll
    for (int i = 1; i < 8; i++) tot += s_red[i];

#pragma unroll
    for (int r = 0; r < 4; r++) {
        const int n = t + r * 256;
        out_prec[(size_t)b * NN + n] =
            (1.f - tot) * prec[(size_t)b * NN + n] + wv[r];
    }
}

// One block per (b, i) row. 256 threads, one float4 each over j.
// link[b,i,j] = (1 - w[b,i] - w[b,j]) * L[b,i,j] + w[b,i] * p[b,j]; diag = 0.
__global__ __launch_bounds__(256) void wh_link_kernel(
    const float* __restrict__ L, const float* __restrict__ w,
    const float* __restrict__ p, float* __restrict__ out)
{
    const size_t row = blockIdx.x;            // b*N + i
    const int b = (int)(row >> 10);
    const int i = (int)(row & 1023);
    const int j4 = threadIdx.x;               // 0..255

    const float wi = __ldg(w + row);
    const float4 l  = reinterpret_cast<const float4*>(L)[row * 256 + j4];
    const float4 wj = reinterpret_cast<const float4*>(w)[(size_t)b * 256 + j4];
    const float4 pj = reinterpret_cast<const float4*>(p)[(size_t)b * 256 + j4];

    float4 o;
    o.x = (1.f - wi - wj.x) * l.x + wi * pj.x;
    o.y = (1.f - wi - wj.y) * l.y + wi * pj.y;
    o.z = (1.f - wi - wj.z) * l.z + wi * pj.z;
    o.w = (1.f - wi - wj.w) * l.w + wi * pj.w;

    if (j4 == (i >> 2)) ((float*)&o)[i & 3] = 0.f;

    reinterpret_cast<float4*>(out)[row * 256 + j4] = o;
}

extern "C" void kernel_launch(void* const* d_in, const int* in_sizes, int n_in,
                              void* d_out, int out_size)
{
    const float* w_key  = (const float*)d_in[0];
    const float* w_beta = (const float*)d_in[1];
    // d_in[2] = e_vector (unused by outputs), d_in[3] = w_vector (unused)
    const float* a_gate = (const float*)d_in[4];
    const float* w_gate = (const float*)d_in[5];
    const float* alloc  = (const float*)d_in[6];
    const float* memory = (const float*)d_in[7];
    const float* linkm  = (const float*)d_in[8];
    const float* prec   = (const float*)d_in[9];

    float* out = (float*)d_out;
    float* out_w    = out;                                   // B*N
    float* out_mem  = out + (size_t)BB * NN;                 // B*N*W
    float* out_link = out_mem + (size_t)BB * NN * WW;        // B*N*N
    float* out_prec = out_link + (size_t)BB * NN * NN;       // B*N

    wh_weights_kernel<<<BB, 256>>>(w_key, w_beta, a_gate, w_gate,
                                   alloc, memory, prec, out_w, out_prec);

    cudaMemcpyAsync(out_mem, memory, (size_t)BB * NN * WW * sizeof(float),
                    cudaMemcpyDeviceToDevice);

    wh_link_kernel<<<BB * NN, 256>>>(linkm, out_w, prec, out_link);
}

// round 2
// speedup vs baseline: 1.6832x; 1.6832x over previous
#include <cuda_runtime.h>
#include <math.h>

#define EPSF 1e-8f
#define BB 64
#define NN 1024
#define WW 128

__device__ float g_sim[BB * NN];   // scratch: similarity logits

__device__ __forceinline__ float warp_sum(float v) {
#pragma unroll
    for (int o = 16; o; o >>= 1) v += __shfl_xor_sync(0xffffffffu, v, o);
    return v;
}
__device__ __forceinline__ float warp_max(float v) {
#pragma unroll
    for (int o = 16; o; o >>= 1) v = fmaxf(v, __shfl_xor_sync(0xffffffffu, v, o));
    return v;
}

// Phase 1: cosine similarity * beta. One warp per memory row.
// grid = B*N/8 blocks of 256 threads (8 warps); 8 consecutive rows share a batch.
__global__ __launch_bounds__(256) void wh_sim_kernel(
    const float* __restrict__ w_key, const float* __restrict__ w_beta,
    const float* __restrict__ memory)
{
    const int t = threadIdx.x;
    const int lane = t & 31;
    const int warp = t >> 5;
    const size_t row0 = (size_t)blockIdx.x * 8;   // global row = b*N + n
    const int b = (int)(row0 >> 10);              // N = 1024

    __shared__ float s_key[WW];
    if (t < WW) s_key[t] = w_key[b * WW + t];
    __syncthreads();

    // key norm (redundant per warp; cheap)
    float ks = 0.f;
#pragma unroll
    for (int i = lane; i < WW; i += 32) { float v = s_key[i]; ks += v * v; }
    ks = warp_sum(ks);
    const float knorm = sqrtf(ks) + EPSF;

    const float bx = w_beta[b];
    const float beta = 1.f + (bx > 20.f ? bx : log1pf(expf(bx)));

    const float4 k4 = reinterpret_cast<const float4*>(s_key)[lane];
    const size_t row = row0 + warp;
    const float4 m = reinterpret_cast<const float4*>(memory + row * WW)[lane];

    float dot = m.x * k4.x + m.y * k4.y + m.z * k4.z + m.w * k4.w;
    float sq  = m.x * m.x + m.y * m.y + m.z * m.z + m.w * m.w;
    dot = warp_sum(dot);
    sq  = warp_sum(sq);
    if (lane == 0)
        g_sim[row] = beta * dot / ((sqrtf(sq) + EPSF) * knorm);
}

// Phase 2: softmax over N, gated write weights, precedence. One block per batch.
__global__ __launch_bounds__(256) void wh_weights_kernel(
    const float* __restrict__ a_gate, const float* __restrict__ w_gate,
    const float* __restrict__ alloc, const float* __restrict__ prec,
    float* __restrict__ out_w, float* __restrict__ out_prec)
{
    const int b = blockIdx.x;
    const int t = threadIdx.x;
    const int lane = t & 31;
    const int warp = t >> 5;

    __shared__ float s_red[8];

    float sv[4];
    float mx = -INFINITY;
#pragma unroll
    for (int r = 0; r < 4; r++) {
        sv[r] = g_sim[(size_t)b * NN + t + r * 256];
        mx = fmaxf(mx, sv[r]);
    }
    mx = warp_max(mx);
    if (lane == 0) s_red[warp] = mx;
    __syncthreads();
    mx = s_red[0];
#pragma unroll
    for (int i = 1; i < 8; i++) mx = fmaxf(mx, s_red[i]);

    float ev[4];
    float esum = 0.f;
#pragma unroll
    for (int r = 0; r < 4; r++) {
        float e = expf(sv[r] - mx);
        ev[r] = e;
        esum += e;
    }
    __syncthreads();
    esum = warp_sum(esum);
    if (lane == 0) s_red[warp] = esum;
    __syncthreads();
    float ssum = s_red[0];
#pragma unroll
    for (int i = 1; i < 8; i++) ssum += s_red[i];
    const float inv = 1.f / ssum;

    const float wg = 1.f / (1.f + expf(-w_gate[b]));
    const float ag = 1.f / (1.f + expf(-a_gate[b]));

    float wv[4];
    float wsum = 0.f;
#pragma unroll
    for (int r = 0; r < 4; r++) {
        const int n = t + r * 256;
        const float c = ev[r] * inv;
        const float w = wg * (ag * alloc[(size_t)b * NN + n] + (1.f - ag) * c);
        wv[r] = w;
        wsum += w;
        out_w[(size_t)b * NN + n] = w;
    }
    __syncthreads();
    wsum = warp_sum(wsum);
    if (lane == 0) s_red[warp] = wsum;
    __syncthreads();
    float tot = s_red[0];
#pragma unroll
    for (int i = 1; i < 8; i++) tot += s_red[i];

#pragma unroll
    for (int r = 0; r < 4; r++) {
        const int n = t + r * 256;
        out_prec[(size_t)b * NN + n] =
            (1.f - tot) * prec[(size_t)b * NN + n] + wv[r];
    }
}

// Link update: 2 rows per block, 256 threads, one float4 per thread per row.
// link[b,i,j] = (1 - w[b,i] - w[b,j]) * L[b,i,j] + w[b,i] * p[b,j]; diag = 0.
__global__ __launch_bounds__(256) void wh_link_kernel(
    const float* __restrict__ L, const float* __restrict__ w,
    const float* __restrict__ p, float* __restrict__ out)
{
    const size_t row0 = (size_t)blockIdx.x * 2;   // b*N + i0
    const int b = (int)(row0 >> 10);
    const int i0 = (int)(row0 & 1023);
    const int i1 = i0 + 1;
    const int j4 = threadIdx.x;

    const float wi0 = __ldg(w + row0);
    const float wi1 = __ldg(w + row0 + 1);
    const float4 l0 = reinterpret_cast<const float4*>(L)[row0 * 256 + j4];
    const float4 l1 = reinterpret_cast<const float4*>(L)[(row0 + 1) * 256 + j4];
    const float4 wj = reinterpret_cast<const float4*>(w)[(size_t)b * 256 + j4];
    const float4 pj = reinterpret_cast<const float4*>(p)[(size_t)b * 256 + j4];

    float4 o0, o1;
    o0.x = (1.f - wi0 - wj.x) * l0.x + wi0 * pj.x;
    o0.y = (1.f - wi0 - wj.y) * l0.y + wi0 * pj.y;
    o0.z = (1.f - wi0 - wj.z) * l0.z + wi0 * pj.z;
    o0.w = (1.f - wi0 - wj.w) * l0.w + wi0 * pj.w;
    o1.x = (1.f - wi1 - wj.x) * l1.x + wi1 * pj.x;
    o1.y = (1.f - wi1 - wj.y) * l1.y + wi1 * pj.y;
    o1.z = (1.f - wi1 - wj.z) * l1.z + wi1 * pj.z;
    o1.w = (1.f - wi1 - wj.w) * l1.w + wi1 * pj.w;

    if (j4 == (i0 >> 2)) ((float*)&o0)[i0 & 3] = 0.f;
    if (j4 == (i1 >> 2)) ((float*)&o1)[i1 & 3] = 0.f;

    reinterpret_cast<float4*>(out)[row0 * 256 + j4] = o0;
    reinterpret_cast<float4*>(out)[(row0 + 1) * 256 + j4] = o1;
}

extern "C" void kernel_launch(void* const* d_in, const int* in_sizes, int n_in,
                              void* d_out, int out_size)
{
    const float* w_key  = (const float*)d_in[0];
    const float* w_beta = (const float*)d_in[1];
    // d_in[2] = e_vector (unused), d_in[3] = w_vector (unused)
    const float* a_gate = (const float*)d_in[4];
    const float* w_gate = (const float*)d_in[5];
    const float* alloc  = (const float*)d_in[6];
    const float* memory = (const float*)d_in[7];
    const float* linkm  = (const float*)d_in[8];
    const float* prec   = (const float*)d_in[9];

    float* out = (float*)d_out;
    float* out_w    = out;                                   // B*N
    float* out_mem  = out + (size_t)BB * NN;                 // B*N*W
    float* out_link = out_mem + (size_t)BB * NN * WW;        // B*N*N
    float* out_prec = out_link + (size_t)BB * NN * NN;       // B*N

    wh_sim_kernel<<<BB * NN / 8, 256>>>(w_key, w_beta, memory);

    cudaMemcpyAsync(out_mem, memory, (size_t)BB * NN * WW * sizeof(float),
                    cudaMemcpyDeviceToDevice);

    wh_weights_kernel<<<BB, 256>>>(a_gate, w_gate, alloc, prec,
                                   out_w, out_prec);

    wh_link_kernel<<<BB * NN / 2, 256>>>(linkm, out_w, prec, out_link);
}

// round 3
// speedup vs baseline: 1.8203x; 1.0814x over previous
#include <cuda_runtime.h>
#include <math.h>

#define EPSF 1e-8f
#define BB 64
#define NN 1024
#define WW 128

__device__ float g_sim[BB * NN];   // scratch: similarity logits

__device__ __forceinline__ float warp_sum(float v) {
#pragma unroll
    for (int o = 16; o; o >>= 1) v += __shfl_xor_sync(0xffffffffu, v, o);
    return v;
}
__device__ __forceinline__ float warp_max(float v) {
#pragma unroll
    for (int o = 16; o; o >>= 1) v = fmaxf(v, __shfl_xor_sync(0xffffffffu, v, o));
    return v;
}

// Phase 1: cosine similarity * beta, fused with memory -> out_mem passthrough.
// 4 rows per warp, 8 warps per block => 32 rows/block, grid = B*N/32 = 2048... (256)
__global__ __launch_bounds__(256) void wh_sim_kernel(
    const float* __restrict__ w_key, const float* __restrict__ w_beta,
    const float* __restrict__ memory, float* __restrict__ out_mem)
{
    const int t = threadIdx.x;
    const int lane = t & 31;
    const int warp = t >> 5;
    // block handles 32 consecutive rows within one batch (1024 % 32 == 0)
    const size_t row0 = ((size_t)blockIdx.x * 8 + warp) * 4;  // first of 4 rows
    const int b = (int)(row0 >> 10);

    __shared__ float s_key[WW];
    if (t < WW) s_key[t] = w_key[b * WW + t];
    __syncthreads();

    // key norm (redundant per warp; cheap)
    float ks = 0.f;
#pragma unroll
    for (int i = lane; i < WW; i += 32) { float v = s_key[i]; ks += v * v; }
    ks = warp_sum(ks);
    const float knorm = sqrtf(ks) + EPSF;

    const float bx = w_beta[b];
    const float beta = 1.f + (bx > 20.f ? bx : log1pf(expf(bx)));

    const float4 k4 = reinterpret_cast<const float4*>(s_key)[lane];

    // batched loads: 4 independent rows in flight
    float4 m[4];
#pragma unroll
    for (int r = 0; r < 4; r++)
        m[r] = reinterpret_cast<const float4*>(memory + (row0 + r) * WW)[lane];

    // fused passthrough copy
#pragma unroll
    for (int r = 0; r < 4; r++)
        reinterpret_cast<float4*>(out_mem + (row0 + r) * WW)[lane] = m[r];

    float dot[4], sq[4];
#pragma unroll
    for (int r = 0; r < 4; r++) {
        dot[r] = m[r].x * k4.x + m[r].y * k4.y + m[r].z * k4.z + m[r].w * k4.w;
        sq[r]  = m[r].x * m[r].x + m[r].y * m[r].y + m[r].z * m[r].z + m[r].w * m[r].w;
    }

    // 8 interleaved butterfly reductions (independent -> latency hidden)
#pragma unroll
    for (int o = 16; o; o >>= 1) {
#pragma unroll
        for (int r = 0; r < 4; r++) {
            dot[r] += __shfl_xor_sync(0xffffffffu, dot[r], o);
            sq[r]  += __shfl_xor_sync(0xffffffffu, sq[r], o);
        }
    }

    if (lane == 0) {
#pragma unroll
        for (int r = 0; r < 4; r++)
            g_sim[row0 + r] = beta * dot[r] / ((sqrtf(sq[r]) + EPSF) * knorm);
    }
}

// Phase 2: softmax over N, gated write weights, precedence. One block per batch.
__global__ __launch_bounds__(256) void wh_weights_kernel(
    const float* __restrict__ a_gate, const float* __restrict__ w_gate,
    const float* __restrict__ alloc, const float* __restrict__ prec,
    float* __restrict__ out_w, float* __restrict__ out_prec)
{
    const int b = blockIdx.x;
    const int t = threadIdx.x;
    const int lane = t & 31;
    const int warp = t >> 5;

    __shared__ float s_red[8];

    float sv[4];
    float mx = -INFINITY;
#pragma unroll
    for (int r = 0; r < 4; r++) {
        sv[r] = g_sim[(size_t)b * NN + t + r * 256];
        mx = fmaxf(mx, sv[r]);
    }
    mx = warp_max(mx);
    if (lane == 0) s_red[warp] = mx;
    __syncthreads();
    mx = s_red[0];
#pragma unroll
    for (int i = 1; i < 8; i++) mx = fmaxf(mx, s_red[i]);

    float ev[4];
    float esum = 0.f;
#pragma unroll
    for (int r = 0; r < 4; r++) {
        float e = expf(sv[r] - mx);
        ev[r] = e;
        esum += e;
    }
    __syncthreads();
    esum = warp_sum(esum);
    if (lane == 0) s_red[warp] = esum;
    __syncthreads();
    float ssum = s_red[0];
#pragma unroll
    for (int i = 1; i < 8; i++) ssum += s_red[i];
    const float inv = 1.f / ssum;

    const float wg = 1.f / (1.f + expf(-w_gate[b]));
    const float ag = 1.f / (1.f + expf(-a_gate[b]));

    float wv[4];
    float wsum = 0.f;
#pragma unroll
    for (int r = 0; r < 4; r++) {
        const int n = t + r * 256;
        const float c = ev[r] * inv;
        const float w = wg * (ag * alloc[(size_t)b * NN + n] + (1.f - ag) * c);
        wv[r] = w;
        wsum += w;
        out_w[(size_t)b * NN + n] = w;
    }
    __syncthreads();
    wsum = warp_sum(wsum);
    if (lane == 0) s_red[warp] = wsum;
    __syncthreads();
    float tot = s_red[0];
#pragma unroll
    for (int i = 1; i < 8; i++) tot += s_red[i];

#pragma unroll
    for (int r = 0; r < 4; r++) {
        const int n = t + r * 256;
        out_prec[(size_t)b * NN + n] =
            (1.f - tot) * prec[(size_t)b * NN + n] + wv[r];
    }
}

// Link update: 4 rows per block, 256 threads, one float4 per thread per row.
// link[b,i,j] = (1 - w[b,i] - w[b,j]) * L[b,i,j] + w[b,i] * p[b,j]; diag = 0.
__global__ __launch_bounds__(256) void wh_link_kernel(
    const float* __restrict__ L, const float* __restrict__ w,
    const float* __restrict__ p, float* __restrict__ out)
{
    const size_t row0 = (size_t)blockIdx.x * 4;   // b*N + i0
    const int b = (int)(row0 >> 10);
    const int i0 = (int)(row0 & 1023);
    const int j4 = threadIdx.x;

    float wi[4];
#pragma unroll
    for (int r = 0; r < 4; r++) wi[r] = __ldg(w + row0 + r);

    float4 l[4];
#pragma unroll
    for (int r = 0; r < 4; r++)
        l[r] = __ldcs(reinterpret_cast<const float4*>(L) + (row0 + r) * 256 + j4);

    const float4 wj = __ldg(reinterpret_cast<const float4*>(w) + (size_t)b * 256 + j4);
    const float4 pj = __ldg(reinterpret_cast<const float4*>(p) + (size_t)b * 256 + j4);

#pragma unroll
    for (int r = 0; r < 4; r++) {
        float4 o;
        o.x = (1.f - wi[r] - wj.x) * l[r].x + wi[r] * pj.x;
        o.y = (1.f - wi[r] - wj.y) * l[r].y + wi[r] * pj.y;
        o.z = (1.f - wi[r] - wj.z) * l[r].z + wi[r] * pj.z;
        o.w = (1.f - wi[r] - wj.w) * l[r].w + wi[r] * pj.w;

        const int i = i0 + r;
        if (j4 == (i >> 2)) ((float*)&o)[i & 3] = 0.f;

        __stcs(reinterpret_cast<float4*>(out) + (row0 + r) * 256 + j4, o);
    }
}

extern "C" void kernel_launch(void* const* d_in, const int* in_sizes, int n_in,
                              void* d_out, int out_size)
{
    const float* w_key  = (const float*)d_in[0];
    const float* w_beta = (const float*)d_in[1];
    // d_in[2] = e_vector (unused), d_in[3] = w_vector (unused)
    const float* a_gate = (const float*)d_in[4];
    const float* w_gate = (const float*)d_in[5];
    const float* alloc  = (const float*)d_in[6];
    const float* memory = (const float*)d_in[7];
    const float* linkm  = (const float*)d_in[8];
    const float* prec   = (const float*)d_in[9];

    float* out = (float*)d_out;
    float* out_w    = out;                                   // B*N
    float* out_mem  = out + (size_t)BB * NN;                 // B*N*W
    float* out_link = out_mem + (size_t)BB * NN * WW;        // B*N*N
    float* out_prec = out_link + (size_t)BB * NN * NN;       // B*N

    wh_sim_kernel<<<BB * NN / 32, 256>>>(w_key, w_beta, memory, out_mem);

    wh_weights_kernel<<<BB, 256>>>(a_gate, w_gate, alloc, prec,
                                   out_w, out_prec);

    wh_link_kernel<<<BB * NN / 4, 256>>>(linkm, out_w, prec, out_link);
}

// round 4
// speedup vs baseline: 1.8263x; 1.0033x over previous
#include <cuda_runtime.h>
#include <math.h>

#define EPSF 1e-8f
#define BB 64
#define NN 1024
#define WW 128

__device__ float g_sim[BB * NN];   // scratch: similarity logits

__device__ __forceinline__ float warp_sum(float v) {
#pragma unroll
    for (int o = 16; o; o >>= 1) v += __shfl_xor_sync(0xffffffffu, v, o);
    return v;
}
__device__ __forceinline__ float warp_max(float v) {
#pragma unroll
    for (int o = 16; o; o >>= 1) v = fmaxf(v, __shfl_xor_sync(0xffffffffu, v, o));
    return v;
}

// Phase 1: cosine similarity * beta, fused with memory -> out_mem passthrough.
// 8 rows per warp (two batches of 4), 8 warps/block => 64 rows/block.
// grid = B*N/64 = 1024 blocks -> fits in ONE wave at ~7 blocks/SM.
__global__ __launch_bounds__(256) void wh_sim_kernel(
    const float* __restrict__ w_key, const float* __restrict__ w_beta,
    const float* __restrict__ memory, float* __restrict__ out_mem)
{
    const int t = threadIdx.x;
    const int lane = t & 31;
    const int warp = t >> 5;
    // block handles 64 consecutive rows within one batch (1024 % 64 == 0)
    const size_t row0 = ((size_t)blockIdx.x * 8 + warp) * 8;  // first of 8 rows
    const int b = (int)(row0 >> 10);

    __shared__ float s_key[WW];
    if (t < WW) s_key[t] = w_key[b * WW + t];
    __syncthreads();

    // key norm (redundant per warp; cheap)
    float ks = 0.f;
#pragma unroll
    for (int i = lane; i < WW; i += 32) { float v = s_key[i]; ks += v * v; }
    ks = warp_sum(ks);
    const float knorm = sqrtf(ks) + EPSF;

    const float bx = w_beta[b];
    const float beta = 1.f + (bx > 20.f ? bx : log1pf(expf(bx)));
    const float4 k4 = reinterpret_cast<const float4*>(s_key)[lane];

    // ---- batch A: rows row0..row0+3 ----
    float4 mA[4];
#pragma unroll
    for (int r = 0; r < 4; r++)
        mA[r] = __ldcs(reinterpret_cast<const float4*>(memory + (row0 + r) * WW) + lane);

    // ---- batch B loads issued early: rows row0+4..row0+7 ----
    float4 mB[4];
#pragma unroll
    for (int r = 0; r < 4; r++)
        mB[r] = __ldcs(reinterpret_cast<const float4*>(memory + (row0 + 4 + r) * WW) + lane);

    // batch A: passthrough + dot/sq + reduce (latency hidden by B loads in flight)
#pragma unroll
    for (int r = 0; r < 4; r++)
        __stcs(reinterpret_cast<float4*>(out_mem + (row0 + r) * WW) + lane, mA[r]);

    float dot[4], sq[4];
#pragma unroll
    for (int r = 0; r < 4; r++) {
        dot[r] = mA[r].x * k4.x + mA[r].y * k4.y + mA[r].z * k4.z + mA[r].w * k4.w;
        sq[r]  = mA[r].x * mA[r].x + mA[r].y * mA[r].y + mA[r].z * mA[r].z + mA[r].w * mA[r].w;
    }
#pragma unroll
    for (int o = 16; o; o >>= 1) {
#pragma unroll
        for (int r = 0; r < 4; r++) {
            dot[r] += __shfl_xor_sync(0xffffffffu, dot[r], o);
            sq[r]  += __shfl_xor_sync(0xffffffffu, sq[r], o);
        }
    }
    if (lane == 0) {
#pragma unroll
        for (int r = 0; r < 4; r++)
            g_sim[row0 + r] = beta * dot[r] / ((sqrtf(sq[r]) + EPSF) * knorm);
    }

    // batch B: passthrough + dot/sq + reduce (accumulator regs reused)
#pragma unroll
    for (int r = 0; r < 4; r++)
        __stcs(reinterpret_cast<float4*>(out_mem + (row0 + 4 + r) * WW) + lane, mB[r]);

#pragma unroll
    for (int r = 0; r < 4; r++) {
        dot[r] = mB[r].x * k4.x + mB[r].y * k4.y + mB[r].z * k4.z + mB[r].w * k4.w;
        sq[r]  = mB[r].x * mB[r].x + mB[r].y * mB[r].y + mB[r].z * mB[r].z + mB[r].w * mB[r].w;
    }
#pragma unroll
    for (int o = 16; o; o >>= 1) {
#pragma unroll
        for (int r = 0; r < 4; r++) {
            dot[r] += __shfl_xor_sync(0xffffffffu, dot[r], o);
            sq[r]  += __shfl_xor_sync(0xffffffffu, sq[r], o);
        }
    }
    if (lane == 0) {
#pragma unroll
        for (int r = 0; r < 4; r++)
            g_sim[row0 + 4 + r] = beta * dot[r] / ((sqrtf(sq[r]) + EPSF) * knorm);
    }
}

// Phase 2: softmax over N, gated write weights, precedence. One block per batch.
__global__ __launch_bounds__(256) void wh_weights_kernel(
    const float* __restrict__ a_gate, const float* __restrict__ w_gate,
    const float* __restrict__ alloc, const float* __restrict__ prec,
    float* __restrict__ out_w, float* __restrict__ out_prec)
{
    const int b = blockIdx.x;
    const int t = threadIdx.x;
    const int lane = t & 31;
    const int warp = t >> 5;

    __shared__ float s_red[8];

    float sv[4];
    float mx = -INFINITY;
#pragma unroll
    for (int r = 0; r < 4; r++) {
        sv[r] = g_sim[(size_t)b * NN + t + r * 256];
        mx = fmaxf(mx, sv[r]);
    }
    mx = warp_max(mx);
    if (lane == 0) s_red[warp] = mx;
    __syncthreads();
    mx = s_red[0];
#pragma unroll
    for (int i = 1; i < 8; i++) mx = fmaxf(mx, s_red[i]);

    float ev[4];
    float esum = 0.f;
#pragma unroll
    for (int r = 0; r < 4; r++) {
        float e = expf(sv[r] - mx);
        ev[r] = e;
        esum += e;
    }
    __syncthreads();
    esum = warp_sum(esum);
    if (lane == 0) s_red[warp] = esum;
    __syncthreads();
    float ssum = s_red[0];
#pragma unroll
    for (int i = 1; i < 8; i++) ssum += s_red[i];
    const float inv = 1.f / ssum;

    const float wg = 1.f / (1.f + expf(-w_gate[b]));
    const float ag = 1.f / (1.f + expf(-a_gate[b]));

    float wv[4];
    float wsum = 0.f;
#pragma unroll
    for (int r = 0; r < 4; r++) {
        const int n = t + r * 256;
        const float c = ev[r] * inv;
        const float w = wg * (ag * alloc[(size_t)b * NN + n] + (1.f - ag) * c);
        wv[r] = w;
        wsum += w;
        out_w[(size_t)b * NN + n] = w;
    }
    __syncthreads();
    wsum = warp_sum(wsum);
    if (lane == 0) s_red[warp] = wsum;
    __syncthreads();
    float tot = s_red[0];
#pragma unroll
    for (int i = 1; i < 8; i++) tot += s_red[i];

#pragma unroll
    for (int r = 0; r < 4; r++) {
        const int n = t + r * 256;
        out_prec[(size_t)b * NN + n] =
            (1.f - tot) * prec[(size_t)b * NN + n] + wv[r];
    }
}

// Link update: 4 rows per block, 256 threads, one float4 per thread per row.
// link[b,i,j] = (1 - w[b,i] - w[b,j]) * L[b,i,j] + w[b,i] * p[b,j]; diag = 0.
__global__ __launch_bounds__(256) void wh_link_kernel(
    const float* __restrict__ L, const float* __restrict__ w,
    const float* __restrict__ p, float* __restrict__ out)
{
    const size_t row0 = (size_t)blockIdx.x * 4;   // b*N + i0
    const int b = (int)(row0 >> 10);
    const int i0 = (int)(row0 & 1023);
    const int j4 = threadIdx.x;

    float wi[4];
#pragma unroll
    for (int r = 0; r < 4; r++) wi[r] = __ldg(w + row0 + r);

    float4 l[4];
#pragma unroll
    for (int r = 0; r < 4; r++)
        l[r] = __ldcs(reinterpret_cast<const float4*>(L) + (row0 + r) * 256 + j4);

    const float4 wj = __ldg(reinterpret_cast<const float4*>(w) + (size_t)b * 256 + j4);
    const float4 pj = __ldg(reinterpret_cast<const float4*>(p) + (size_t)b * 256 + j4);

#pragma unroll
    for (int r = 0; r < 4; r++) {
        float4 o;
        o.x = (1.f - wi[r] - wj.x) * l[r].x + wi[r] * pj.x;
        o.y = (1.f - wi[r] - wj.y) * l[r].y + wi[r] * pj.y;
        o.z = (1.f - wi[r] - wj.z) * l[r].z + wi[r] * pj.z;
        o.w = (1.f - wi[r] - wj.w) * l[r].w + wi[r] * pj.w;

        const int i = i0 + r;
        if (j4 == (i >> 2)) ((float*)&o)[i & 3] = 0.f;

        __stcs(reinterpret_cast<float4*>(out) + (row0 + r) * 256 + j4, o);
    }
}

extern "C" void kernel_launch(void* const* d_in, const int* in_sizes, int n_in,
                              void* d_out, int out_size)
{
    const float* w_key  = (const float*)d_in[0];
    const float* w_beta = (const float*)d_in[1];
    // d_in[2] = e_vector (unused), d_in[3] = w_vector (unused)
    const float* a_gate = (const float*)d_in[4];
    const float* w_gate = (const float*)d_in[5];
    const float* alloc  = (const float*)d_in[6];
    const float* memory = (const float*)d_in[7];
    const float* linkm  = (const float*)d_in[8];
    const float* prec   = (const float*)d_in[9];

    float* out = (float*)d_out;
    float* out_w    = out;                                   // B*N
    float* out_mem  = out + (size_t)BB * NN;                 // B*N*W
    float* out_link = out_mem + (size_t)BB * NN * WW;        // B*N*N
    float* out_prec = out_link + (size_t)BB * NN * NN;       // B*N

    wh_sim_kernel<<<BB * NN / 64, 256>>>(w_key, w_beta, memory, out_mem);

    wh_weights_kernel<<<BB, 256>>>(a_gate, w_gate, alloc, prec,
                                   out_w, out_prec);

    wh_link_kernel<<<BB * NN / 4, 256>>>(linkm, out_w, prec, out_link);
}